// round 16
// baseline (speedup 1.0000x reference)
#include <cuda_runtime.h>
#include <cuda_fp16.h>

#define DIM    128
#define NPROJ  256
#define TPB    256
#define TOK_PER_CTA 128     // 8 warps x 16 tokens
#define TAU    0.025f       // ~9 sigma of 1-term fp16 kp error
#define SCALE  ((float)(1.2533141373155003 / 256.0))   // sqrt(pi/2)/NPROJ
#define SPACK_BYTES (NPROJ * 32 * 8)   // 64 KB

// S_hi (fp16) repacked lane-contiguous, two n-halves per uint4:
// uint4 index = nt*256 + j*32 + lane   (nt: 16-proj tile, j: k-step, lane = g*4+tg)
//   n_a = nt*16 + g, n_b = n_a + 8, k0 = tg*2 + 16*j
//   v.x = hi(S[n_a][k0],  S[n_a][k0+1])   v.y = hi(S[n_a][k0+8], S[n_a][k0+9])
//   v.z = hi(S[n_b][k0],  S[n_b][k0+1])   v.w = hi(S[n_b][k0+8], S[n_b][k0+9])
// For fixed (nt,j) the 32 lanes read 512 contiguous bytes.
__device__ uint4 g_Sp[4096];   // 64 KB (global master; staged to smem per CTA)

__device__ __forceinline__ unsigned pack_h2(float x, float y) {
    __half2 h = __floats2half2_rn(x, y);
    return *reinterpret_cast<unsigned*>(&h);
}

__global__ void prep_S(const float* __restrict__ S) {
    int idx = blockIdx.x * blockDim.x + threadIdx.x;   // 0..4095
    int lane = idx & 31, j = (idx >> 5) & 7, nt = idx >> 8;
    int g = lane >> 2, tg = lane & 3;
    int n_a = nt * 16 + g, n_b = n_a + 8;
    int k0  = tg * 2 + 16 * j;
    const float* ra = S + (size_t)n_a * DIM;
    const float* rb = S + (size_t)n_b * DIM;
    uint4 v;
    v.x = pack_h2(ra[k0], ra[k0 + 1]);
    v.y = pack_h2(ra[k0 + 8], ra[k0 + 9]);
    v.z = pack_h2(rb[k0], rb[k0 + 1]);
    v.w = pack_h2(rb[k0 + 8], rb[k0 + 9]);
    g_Sp[idx] = v;
}

// mma.sync m16n8k16 fp16 -> f32 accumulate (baseline sm_80 ISA)
__device__ __forceinline__ void mma_f16(float* c, const unsigned* a,
                                        unsigned b0, unsigned b1) {
    asm volatile(
        "mma.sync.aligned.m16n8k16.row.col.f32.f16.f16.f32 "
        "{%0,%1,%2,%3}, {%4,%5,%6,%7}, {%8,%9}, {%0,%1,%2,%3};"
        : "+f"(c[0]), "+f"(c[1]), "+f"(c[2]), "+f"(c[3])
        : "r"(a[0]), "r"(a[1]), "r"(a[2]), "r"(a[3]), "r"(b0), "r"(b1));
}

__global__ void __launch_bounds__(TPB, 2)
qjl_mma_kernel(const float* __restrict__ Q,
               const float* __restrict__ K,
               const float* __restrict__ S,
               float* __restrict__ out,
               int ntok)
{
    extern __shared__ uint4 sB[];          // 4096 uint4 = 64 KB staged S-pack

    const int tid  = threadIdx.x;
    const int lane = tid & 31;
    const int w    = tid >> 5;
    const int g    = lane >> 2;            // row group / B column
    const int tg   = lane & 3;             // k-pair / C column pair

    const int base = blockIdx.x * TOK_PER_CTA + w * 16;
    const int tok0 = base + g, tok1 = base + g + 8;
    const int t0c  = tok0 < ntok ? tok0 : ntok - 1;
    const int t1c  = tok1 < ntok ? tok1 : ntok - 1;

    // ---- stage the 64 KB S-pack into shared memory (coalesced uint4) ----
    {
        const uint4* src = (const uint4*)g_Sp;
#pragma unroll
        for (int i = 0; i < 16; ++i) sB[tid + TPB * i] = src[tid + TPB * i];
    }

    // ---- A fragments in registers: q_hi, k_hi (fp16), K-dim = 128 (64 regs) ----
    unsigned qh[8][4], kh[8][4];
    {
        const float* q0 = Q + (size_t)t0c * DIM;
        const float* q1 = Q + (size_t)t1c * DIM;
        const float* k0 = K + (size_t)t0c * DIM;
        const float* k1 = K + (size_t)t1c * DIM;
#pragma unroll
        for (int j = 0; j < 8; ++j) {
            const int c = tg * 2 + 16 * j;
            float2 v;
            v = *(const float2*)(q0 + c);     qh[j][0] = pack_h2(v.x, v.y);
            v = *(const float2*)(q1 + c);     qh[j][1] = pack_h2(v.x, v.y);
            v = *(const float2*)(q0 + c + 8); qh[j][2] = pack_h2(v.x, v.y);
            v = *(const float2*)(q1 + c + 8); qh[j][3] = pack_h2(v.x, v.y);
            v = *(const float2*)(k0 + c);     kh[j][0] = pack_h2(v.x, v.y);
            v = *(const float2*)(k1 + c);     kh[j][1] = pack_h2(v.x, v.y);
            v = *(const float2*)(k0 + c + 8); kh[j][2] = pack_h2(v.x, v.y);
            v = *(const float2*)(k1 + c + 8); kh[j][3] = pack_h2(v.x, v.y);
        }
    }

    __syncthreads();                       // S-pack visible to all warps

    float acc0 = 0.f, acc1 = 0.f;

    // ---- 16 projection tiles of n=16; 4 MMAs/k-step over 4 INDEPENDENT chains ----
#pragma unroll 1
    for (int nt = 0; nt < 16; ++nt) {
        float cqa[4] = {0.f, 0.f, 0.f, 0.f};   // q_hi * S_hi  (n-half a)
        float cka[4] = {0.f, 0.f, 0.f, 0.f};   // k_hi * S_hi  (n-half a)
        float cqb[4] = {0.f, 0.f, 0.f, 0.f};   // (n-half b)
        float ckb[4] = {0.f, 0.f, 0.f, 0.f};

        const uint4* bp = sB + nt * 256 + lane;
        uint4 bc = bp[0];                      // rolling 2-deep B buffer
#pragma unroll
        for (int j = 0; j < 8; ++j) {
            uint4 bn;
            if (j < 7) bn = bp[(j + 1) * 32];
            mma_f16(cqa, qh[j], bc.x, bc.y);
            mma_f16(cka, kh[j], bc.x, bc.y);
            mma_f16(cqb, qh[j], bc.z, bc.w);
            mma_f16(ckb, kh[j], bc.z, bc.w);
            if (j < 7) bc = bn;
        }

        const int pa = nt * 16 + tg * 2;       // n-half a projection base (b: +8)
        // cka[i]: tok(i&2? t1:t0), proj pa+(i&1);  ckb[i]: same + 8

        // ---- single-ballot warp-cooperative exact-fp32 sign fix-up ----
        float mn = fminf(fminf(fminf(fabsf(cka[0]), fabsf(cka[1])),
                               fminf(fabsf(cka[2]), fabsf(cka[3]))),
                         fminf(fminf(fabsf(ckb[0]), fabsf(ckb[1])),
                               fminf(fabsf(ckb[2]), fabsf(ckb[3]))));
        unsigned m = __ballot_sync(0xffffffffu, mn < TAU);
        if (m) {                               // rare, warp-uniform branch
            unsigned fl = 0;
#pragma unroll
            for (int p = 0; p < 4; ++p) {
                if (fabsf(cka[p]) < TAU) fl |= 1u << p;
                if (fabsf(ckb[p]) < TAU) fl |= 1u << (4 + p);
            }
            while (m) {
                int src = __ffs(m) - 1; m &= m - 1;
                unsigned sfl = __shfl_sync(0xffffffffu, fl, src);
                int spa = __shfl_sync(0xffffffffu, pa, src);
                int st0 = __shfl_sync(0xffffffffu, t0c, src);
                int st1 = __shfl_sync(0xffffffffu, t1c, src);
                while (sfl) {                  // p is warp-uniform here
                    int p = __ffs(sfl) - 1; sfl &= sfl - 1;
                    int stok  = (p & 2) ? st1 : st0;
                    int sproj = spa + (p & 1) + ((p & 4) ? 8 : 0);
                    float4 kv = *(const float4*)(K + (size_t)stok  * DIM + lane * 4);
                    float4 sv = *(const float4*)(S + (size_t)sproj * DIM + lane * 4);
                    float part = fmaf(kv.x, sv.x,
                                 fmaf(kv.y, sv.y,
                                 fmaf(kv.z, sv.z, kv.w * sv.w)));
#pragma unroll
                    for (int o = 16; o; o >>= 1)
                        part += __shfl_xor_sync(0xffffffffu, part, o);
                    if (lane == src) {
                        switch (p) {           // p uniform -> uniform branch
                            case 0: cka[0] = part; break;
                            case 1: cka[1] = part; break;
                            case 2: cka[2] = part; break;
                            case 3: cka[3] = part; break;
                            case 4: ckb[0] = part; break;
                            case 5: ckb[1] = part; break;
                            case 6: ckb[2] = part; break;
                            case 7: ckb[3] = part; break;
                        }
                    }
                }
            }
        }

        // ---- accumulate qp * sign(kp);  jnp.sign(0) == 0 ----
#pragma unroll
        for (int p = 0; p < 4; ++p) {
            float ta = __uint_as_float(__float_as_uint(cqa[p]) ^
                                       (__float_as_uint(cka[p]) & 0x80000000u));
            if (cka[p] != 0.f) { if (p & 2) acc1 += ta; else acc0 += ta; }
            float tb = __uint_as_float(__float_as_uint(cqb[p]) ^
                                       (__float_as_uint(ckb[p]) & 0x80000000u));
            if (ckb[p] != 0.f) { if (p & 2) acc1 += tb; else acc0 += tb; }
        }
    }

    // ---- final reduction over the 4 lanes of each row group ----
    acc0 += __shfl_xor_sync(0xffffffffu, acc0, 1);
    acc0 += __shfl_xor_sync(0xffffffffu, acc0, 2);
    acc1 += __shfl_xor_sync(0xffffffffu, acc1, 1);
    acc1 += __shfl_xor_sync(0xffffffffu, acc1, 2);

    if (tg == 0) {
        if (tok0 < ntok) out[tok0] = SCALE * acc0;
        if (tok1 < ntok) out[tok1] = SCALE * acc1;
    }
}

extern "C" void kernel_launch(void* const* d_in, const int* in_sizes, int n_in,
                              void* d_out, int out_size) {
    // Identify S by element count (NPROJ*DIM = 32768); q precedes k among the rest.
    int s_idx = 2;
    for (int i = 0; i < n_in; ++i) if (in_sizes[i] == NPROJ * DIM) { s_idx = i; break; }
    int qk[2], wcnt = 0;
    for (int i = 0; i < n_in && wcnt < 2; ++i) if (i != s_idx) qk[wcnt++] = i;

    const float* Q = (const float*)d_in[qk[0]];  // query [B,H,SEQ,DIM] fp32
    const float* K = (const float*)d_in[qk[1]];  // key   [B,H,SEQ,DIM] fp32
    const float* S = (const float*)d_in[s_idx];  // S     [NPROJ,DIM]   fp32
    float* out = (float*)d_out;                  // [B,H,SEQ] fp32

    const int ntok   = in_sizes[qk[0]] / DIM;
    const int blocks = (ntok + TOK_PER_CTA - 1) / TOK_PER_CTA;

    static int smem_set = 0;
    if (!smem_set) {
        cudaFuncSetAttribute(qjl_mma_kernel,
                             cudaFuncAttributeMaxDynamicSharedMemorySize, SPACK_BYTES);
        smem_set = 1;
    }

    prep_S<<<16, 256>>>(S);
    qjl_mma_kernel<<<blocks, TPB, SPACK_BYTES>>>(Q, K, S, out, ntok);
}

// round 17
// speedup vs baseline: 1.4482x; 1.4482x over previous
#include <cuda_runtime.h>
#include <cuda_fp16.h>

#define DIM    128
#define NPROJ  256
#define TPB    256
#define TOK_PER_CTA 128     // 8 warps x 16 tokens
#define TAU    0.025f       // ~9 sigma of 1-term fp16 kp error
#define SCALE  ((float)(1.2533141373155003 / 256.0))   // sqrt(pi/2)/NPROJ
#define SPACK_BYTES (NPROJ * 32 * 8)   // 64 KB
#define GRID_PERSIST 296    // 2 CTAs x 148 SMs

// S_hi (fp16) repacked lane-contiguous, TWO k-steps per uint4:
// uint4 index = nt*128 + j2*32 + lane   (nt: 8-proj tile, j2: k-step pair, lane = g*4+tg)
//   n = nt*8 + g (B column); k-steps j = 2*j2 and 2*j2+1; k0(j) = tg*2 + 16*j
//   v.x = hi(S[n][k0(2j2)],   S[n][k0(2j2)+1])    v.y = hi(S[n][k0(2j2)+8],  ...+9)
//   v.z = hi(S[n][k0(2j2+1)], S[n][k0(2j2+1)+1])  v.w = hi(S[n][k0(2j2+1)+8], ...+9)
// For fixed (nt,j2) the 32 lanes read 512 contiguous bytes.
__device__ uint4 g_Sp[4096];   // 64 KB (global master; staged to smem once per CTA)

__device__ __forceinline__ unsigned pack_h2(float x, float y) {
    __half2 h = __floats2half2_rn(x, y);
    return *reinterpret_cast<unsigned*>(&h);
}

__global__ void prep_S(const float* __restrict__ S) {
    int idx = blockIdx.x * blockDim.x + threadIdx.x;   // 0..4095
    int lane = idx & 31, j2 = (idx >> 5) & 3, nt = idx >> 7;
    int g = lane >> 2, tg = lane & 3;
    int n   = nt * 8 + g;
    int k0a = tg * 2 + 16 * (2 * j2);
    int k0b = tg * 2 + 16 * (2 * j2 + 1);
    const float* row = S + (size_t)n * DIM;
    uint4 v;
    v.x = pack_h2(row[k0a], row[k0a + 1]);
    v.y = pack_h2(row[k0a + 8], row[k0a + 9]);
    v.z = pack_h2(row[k0b], row[k0b + 1]);
    v.w = pack_h2(row[k0b + 8], row[k0b + 9]);
    g_Sp[idx] = v;
}

// mma.sync m16n8k16 fp16 -> f32 accumulate (baseline sm_80 ISA)
__device__ __forceinline__ void mma_f16(float* c, const unsigned* a,
                                        unsigned b0, unsigned b1) {
    asm volatile(
        "mma.sync.aligned.m16n8k16.row.col.f32.f16.f16.f32 "
        "{%0,%1,%2,%3}, {%4,%5,%6,%7}, {%8,%9}, {%0,%1,%2,%3};"
        : "+f"(c[0]), "+f"(c[1]), "+f"(c[2]), "+f"(c[3])
        : "r"(a[0]), "r"(a[1]), "r"(a[2]), "r"(a[3]), "r"(b0), "r"(b1));
}

__global__ void __launch_bounds__(TPB, 2)
qjl_mma_kernel(const float* __restrict__ Q,
               const float* __restrict__ K,
               const float* __restrict__ S,
               float* __restrict__ out,
               int ntok, int ntiles)
{
    extern __shared__ uint4 sB[];          // 4096 uint4 = 64 KB staged S-pack

    const int tid  = threadIdx.x;
    const int lane = tid & 31;
    const int w    = tid >> 5;
    const int g    = lane >> 2;            // row group / B column
    const int tg   = lane & 3;             // k-pair / C column pair

    // ---- stage the 64 KB S-pack into shared memory ONCE per CTA ----
    {
        const uint4* src = (const uint4*)g_Sp;
#pragma unroll
        for (int i = 0; i < 16; ++i) sB[tid + TPB * i] = src[tid + TPB * i];
    }
    __syncthreads();                       // S-pack visible to all warps

    // ---- persistent loop over token tiles ----
    for (int tb = blockIdx.x; tb < ntiles; tb += gridDim.x) {

        const int base = tb * TOK_PER_CTA + w * 16;
        const int tok0 = base + g, tok1 = base + g + 8;
        const int t0c  = tok0 < ntok ? tok0 : ntok - 1;
        const int t1c  = tok1 < ntok ? tok1 : ntok - 1;

        // ---- A fragments in registers: q_hi, k_hi (fp16), K-dim = 128 (64 regs) ----
        unsigned qh[8][4], kh[8][4];
        {
            const float* q0 = Q + (size_t)t0c * DIM;
            const float* q1 = Q + (size_t)t1c * DIM;
            const float* k0 = K + (size_t)t0c * DIM;
            const float* k1 = K + (size_t)t1c * DIM;
#pragma unroll
            for (int j = 0; j < 8; ++j) {
                const int c = tg * 2 + 16 * j;
                float2 v;
                v = *(const float2*)(q0 + c);     qh[j][0] = pack_h2(v.x, v.y);
                v = *(const float2*)(q1 + c);     qh[j][1] = pack_h2(v.x, v.y);
                v = *(const float2*)(q0 + c + 8); qh[j][2] = pack_h2(v.x, v.y);
                v = *(const float2*)(q1 + c + 8); qh[j][3] = pack_h2(v.x, v.y);
                v = *(const float2*)(k0 + c);     kh[j][0] = pack_h2(v.x, v.y);
                v = *(const float2*)(k1 + c);     kh[j][1] = pack_h2(v.x, v.y);
                v = *(const float2*)(k0 + c + 8); kh[j][2] = pack_h2(v.x, v.y);
                v = *(const float2*)(k1 + c + 8); kh[j][3] = pack_h2(v.x, v.y);
            }
        }

        float acc0 = 0.f, acc1 = 0.f;

        // ---- 32 projection tiles of n=8; 2 MMAs/k-step over 2 independent chains ----
#pragma unroll 1
        for (int nt = 0; nt < 32; ++nt) {
            float cq[4] = {0.f, 0.f, 0.f, 0.f};   // q_hi * S_hi
            float ck[4] = {0.f, 0.f, 0.f, 0.f};   // k_hi * S_hi  (sign only)

            // B loads from smem: 4 x LDS.128, hoisted for MLP=4
            const uint4* bp = sB + nt * 128 + lane;
            uint4 b[4];
#pragma unroll
            for (int j2 = 0; j2 < 4; ++j2) b[j2] = bp[j2 * 32];

#pragma unroll
            for (int j2 = 0; j2 < 4; ++j2) {
                mma_f16(cq, qh[2 * j2],     b[j2].x, b[j2].y);
                mma_f16(ck, kh[2 * j2],     b[j2].x, b[j2].y);
                mma_f16(cq, qh[2 * j2 + 1], b[j2].z, b[j2].w);
                mma_f16(ck, kh[2 * j2 + 1], b[j2].z, b[j2].w);
            }

            const int pa = nt * 8 + tg * 2;        // projection base for this lane
            // ck[0],ck[1]: tok0, proj pa,pa+1 ; ck[2],ck[3]: tok1, proj pa,pa+1

            // ---- single-ballot warp-cooperative exact-fp32 sign fix-up ----
            float mn = fminf(fminf(fabsf(ck[0]), fabsf(ck[1])),
                             fminf(fabsf(ck[2]), fabsf(ck[3])));
            unsigned m = __ballot_sync(0xffffffffu, mn < TAU);
            if (m) {                               // rare, warp-uniform branch
                unsigned fl = 0;
#pragma unroll
                for (int p = 0; p < 4; ++p)
                    if (fabsf(ck[p]) < TAU) fl |= 1u << p;
                while (m) {
                    int src = __ffs(m) - 1; m &= m - 1;
                    unsigned sfl = __shfl_sync(0xffffffffu, fl, src);
                    int spa = __shfl_sync(0xffffffffu, pa, src);
                    int st0 = __shfl_sync(0xffffffffu, t0c, src);
                    int st1 = __shfl_sync(0xffffffffu, t1c, src);
                    while (sfl) {                  // p is warp-uniform here
                        int p = __ffs(sfl) - 1; sfl &= sfl - 1;
                        int stok  = (p & 2) ? st1 : st0;
                        int sproj = spa + (p & 1);
                        float4 kv = *(const float4*)(K + (size_t)stok  * DIM + lane * 4);
                        float4 sv = *(const float4*)(S + (size_t)sproj * DIM + lane * 4);
                        float part = fmaf(kv.x, sv.x,
                                     fmaf(kv.y, sv.y,
                                     fmaf(kv.z, sv.z, kv.w * sv.w)));
#pragma unroll
                        for (int o = 16; o; o >>= 1)
                            part += __shfl_xor_sync(0xffffffffu, part, o);
                        if (lane == src) {
                            switch (p) {           // p uniform -> uniform branch
                                case 0: ck[0] = part; break;
                                case 1: ck[1] = part; break;
                                case 2: ck[2] = part; break;
                                case 3: ck[3] = part; break;
                            }
                        }
                    }
                }
            }

            // ---- accumulate qp * sign(kp);  jnp.sign(0) == 0 ----
#pragma unroll
            for (int p = 0; p < 4; ++p) {
                float t = __uint_as_float(__float_as_uint(cq[p]) ^
                                          (__float_as_uint(ck[p]) & 0x80000000u));
                if (ck[p] != 0.f) { if (p & 2) acc1 += t; else acc0 += t; }
            }
        }

        // ---- final reduction over the 4 lanes of each row group ----
        acc0 += __shfl_xor_sync(0xffffffffu, acc0, 1);
        acc0 += __shfl_xor_sync(0xffffffffu, acc0, 2);
        acc1 += __shfl_xor_sync(0xffffffffu, acc1, 1);
        acc1 += __shfl_xor_sync(0xffffffffu, acc1, 2);

        if (tg == 0) {
            if (tok0 < ntok) out[tok0] = SCALE * acc0;
            if (tok1 < ntok) out[tok1] = SCALE * acc1;
        }
    }
}

extern "C" void kernel_launch(void* const* d_in, const int* in_sizes, int n_in,
                              void* d_out, int out_size) {
    // Identify S by element count (NPROJ*DIM = 32768); q precedes k among the rest.
    int s_idx = 2;
    for (int i = 0; i < n_in; ++i) if (in_sizes[i] == NPROJ * DIM) { s_idx = i; break; }
    int qk[2], wcnt = 0;
    for (int i = 0; i < n_in && wcnt < 2; ++i) if (i != s_idx) qk[wcnt++] = i;

    const float* Q = (const float*)d_in[qk[0]];  // query [B,H,SEQ,DIM] fp32
    const float* K = (const float*)d_in[qk[1]];  // key   [B,H,SEQ,DIM] fp32
    const float* S = (const float*)d_in[s_idx];  // S     [NPROJ,DIM]   fp32
    float* out = (float*)d_out;                  // [B,H,SEQ] fp32

    const int ntok   = in_sizes[qk[0]] / DIM;
    const int ntiles = (ntok + TOK_PER_CTA - 1) / TOK_PER_CTA;
    const int grid   = ntiles < GRID_PERSIST ? ntiles : GRID_PERSIST;

    static int smem_set = 0;
    if (!smem_set) {
        cudaFuncSetAttribute(qjl_mma_kernel,
                             cudaFuncAttributeMaxDynamicSharedMemorySize, SPACK_BYTES);
        smem_set = 1;
    }

    prep_S<<<16, 256>>>(S);
    qjl_mma_kernel<<<grid, TPB, SPACK_BYTES>>>(Q, K, S, out, ntok, ntiles);
}